// round 2
// baseline (speedup 1.0000x reference)
#include <cuda_runtime.h>

#define NN 50000
#define NE 800000
#define DIM 256
#define EDIM 64

typedef unsigned long long ull;

// Scratch (static __device__ — no runtime allocation)
__device__ __align__(16) float g_z[NN * DIM];   // z = x + aggr (atomic target)
__device__ __align__(16) float g_h1[NN * DIM];  // hidden after MLP layer 1

__device__ __forceinline__ ull pack2(float x, float y) {
    ull r; asm("mov.b64 %0, {%1,%2};" : "=l"(r) : "f"(x), "f"(y)); return r;
}
__device__ __forceinline__ void unpack2(ull v, float& x, float& y) {
    asm("mov.b64 {%0,%1}, %2;" : "=f"(x), "=f"(y) : "l"(v));
}
// Packed fp32x2 FMA (Blackwell): d = a*b + c elementwise on 2 packed floats
__device__ __forceinline__ ull ffma2(ull a, ull b, ull c) {
    ull d; asm("fma.rn.f32x2 %0, %1, %2, %3;" : "=l"(d) : "l"(a), "l"(b), "l"(c)); return d;
}
// Vector reduction atomic (sm_90+): 4 floats, no return
__device__ __forceinline__ void red4(float* a, float4 v) {
    asm volatile("red.global.add.v4.f32 [%0], {%1,%2,%3,%4};"
                 :: "l"(a), "f"(v.x), "f"(v.y), "f"(v.z), "f"(v.w));
}

// ---------------------------------------------------------------------------
// Kernel 1: z = x   (grid exactly covers NN*DIM/4 float4s: 12500 x 256)
// ---------------------------------------------------------------------------
__global__ __launch_bounds__(256) void k_init(const float4* __restrict__ x) {
    int i = blockIdx.x * 256 + threadIdx.x;
    reinterpret_cast<float4*>(g_z)[i] = x[i];
}

// ---------------------------------------------------------------------------
// Kernel 2: per-edge  msg = relu(x[src] + edge_attr@We + be); red.v4 into g_z[dst]
// Block = 256 threads (8 warps); warp processes 16 edges (2 at a time);
// lane l owns columns {4l..4l+3, 128+4l..128+4l+3} (two float4 segments).
// We in smem as raw float4 == pre-packed f32x2 pairs (little-endian identity).
// edge_index is INT32 (JAX x64-disabled downgrades int64 -> int32).
// ---------------------------------------------------------------------------
__global__ __launch_bounds__(256) void k_edge(
    const float* __restrict__ x, const int* __restrict__ eidx,
    const float* __restrict__ ea, const float* __restrict__ We,
    const float* __restrict__ be)
{
    extern __shared__ char smem[];
    ulonglong2* sW2 = (ulonglong2*)smem;            // [64][64] (64 KB)
    ull* sA = (ull*)(smem + 65536);                 // [8 warps][2 edges][64] packed-dup

    int t = threadIdx.x, w = t >> 5, l = t & 31;

    {   // stage We: 4096 float4s
        const float4* We4 = (const float4*)We;
        float4* sWf = (float4*)smem;
        #pragma unroll
        for (int i = 0; i < 16; i++) sWf[t + 256 * i] = We4[t + 256 * i];
    }
    float4 beA = ((const float4*)be)[l];
    float4 beB = ((const float4*)be)[32 + l];
    __syncthreads();

    ull* A0 = sA + (size_t)(w * 2 + 0) * 64;
    ull* A1 = sA + (size_t)(w * 2 + 1) * 64;
    long long ebase = (long long)blockIdx.x * 128 + (long long)w * 16;

    for (int i = 0; i < 16; i += 2) {
        long long e0 = ebase + i, e1 = e0 + 1;
        __syncwarp();
        // stage edge_attr rows, duplicated into both f32x2 halves
        float2 a0 = ((const float2*)(ea + e0 * EDIM))[l];
        float2 a1 = ((const float2*)(ea + e1 * EDIM))[l];
        A0[2 * l] = pack2(a0.x, a0.x); A0[2 * l + 1] = pack2(a0.y, a0.y);
        A1[2 * l] = pack2(a1.x, a1.x); A1[2 * l + 1] = pack2(a1.y, a1.y);
        __syncwarp();

        ull c00 = 0, c01 = 0, c02 = 0, c03 = 0;
        ull c10 = 0, c11 = 0, c12 = 0, c13 = 0;
        #pragma unroll 16
        for (int k = 0; k < EDIM; k++) {
            ulonglong2 wa = sW2[k * 64 + l];
            ulonglong2 wb = sW2[k * 64 + 32 + l];
            ull a0k = A0[k], a1k = A1[k];
            c00 = ffma2(a0k, wa.x, c00); c01 = ffma2(a0k, wa.y, c01);
            c02 = ffma2(a0k, wb.x, c02); c03 = ffma2(a0k, wb.y, c03);
            c10 = ffma2(a1k, wa.x, c10); c11 = ffma2(a1k, wa.y, c11);
            c12 = ffma2(a1k, wb.x, c12); c13 = ffma2(a1k, wb.y, c13);
        }

        // epilogue edge 0
        {
            long long s = eidx[e0], d = eidx[NE + e0];
            const float4* xr = (const float4*)(x + s * DIM);
            float4 xa = xr[l], xb = xr[32 + l];
            float m0, m1, m2, m3, m4, m5, m6, m7;
            unpack2(c00, m0, m1); unpack2(c01, m2, m3);
            unpack2(c02, m4, m5); unpack2(c03, m6, m7);
            float4 va = make_float4(fmaxf(m0 + xa.x + beA.x, 0.f), fmaxf(m1 + xa.y + beA.y, 0.f),
                                    fmaxf(m2 + xa.z + beA.z, 0.f), fmaxf(m3 + xa.w + beA.w, 0.f));
            float4 vb = make_float4(fmaxf(m4 + xb.x + beB.x, 0.f), fmaxf(m5 + xb.y + beB.y, 0.f),
                                    fmaxf(m6 + xb.z + beB.z, 0.f), fmaxf(m7 + xb.w + beB.w, 0.f));
            red4(g_z + d * DIM + 4 * l, va);
            red4(g_z + d * DIM + 128 + 4 * l, vb);
        }
        // epilogue edge 1
        {
            long long s = eidx[e1], d = eidx[NE + e1];
            const float4* xr = (const float4*)(x + s * DIM);
            float4 xa = xr[l], xb = xr[32 + l];
            float m0, m1, m2, m3, m4, m5, m6, m7;
            unpack2(c10, m0, m1); unpack2(c11, m2, m3);
            unpack2(c12, m4, m5); unpack2(c13, m6, m7);
            float4 va = make_float4(fmaxf(m0 + xa.x + beA.x, 0.f), fmaxf(m1 + xa.y + beA.y, 0.f),
                                    fmaxf(m2 + xa.z + beA.z, 0.f), fmaxf(m3 + xa.w + beA.w, 0.f));
            float4 vb = make_float4(fmaxf(m4 + xb.x + beB.x, 0.f), fmaxf(m5 + xb.y + beB.y, 0.f),
                                    fmaxf(m6 + xb.z + beB.z, 0.f), fmaxf(m7 + xb.w + beB.w, 0.f));
            red4(g_z + d * DIM + 4 * l, va);
            red4(g_z + d * DIM + 128 + 4 * l, vb);
        }
    }
}

// ---------------------------------------------------------------------------
// Kernel 3: h1 = relu(z @ W1 + b1)   [NN,256] @ [256,256]
// Block = 256 threads; warp handles 4 rows; K tiled in 4 chunks of 64 (W in smem).
// ---------------------------------------------------------------------------
__global__ __launch_bounds__(256) void k_mlp1(const float* __restrict__ W1,
                                              const float* __restrict__ b1)
{
    extern __shared__ char smem[];
    ulonglong2* sW2 = (ulonglong2*)smem;   // 64 KB chunk of W
    float4* sWf = (float4*)smem;
    ull* sZ = (ull*)(smem + 65536);        // [32 rows][64] packed-dup

    int t = threadIdx.x, w = t >> 5, l = t & 31;
    int rbase = blockIdx.x * 32 + w * 4;
    int r0 = min(rbase + 0, NN - 1), r1 = min(rbase + 1, NN - 1);
    int r2 = min(rbase + 2, NN - 1), r3 = min(rbase + 3, NN - 1);

    ull acc[4][4];
    #pragma unroll
    for (int j = 0; j < 4; j++) { acc[j][0] = 0; acc[j][1] = 0; acc[j][2] = 0; acc[j][3] = 0; }

    const float4* Wg = (const float4*)W1;
    ull* Z = sZ + (size_t)w * 4 * 64;

    for (int c = 0; c < 4; c++) {
        __syncthreads();
        #pragma unroll
        for (int i = 0; i < 16; i++) sWf[t + 256 * i] = Wg[c * 4096 + t + 256 * i];
        {
            float2 v;
            v = ((const float2*)(g_z + (size_t)r0 * DIM + c * 64))[l];
            Z[0 * 64 + 2 * l] = pack2(v.x, v.x); Z[0 * 64 + 2 * l + 1] = pack2(v.y, v.y);
            v = ((const float2*)(g_z + (size_t)r1 * DIM + c * 64))[l];
            Z[1 * 64 + 2 * l] = pack2(v.x, v.x); Z[1 * 64 + 2 * l + 1] = pack2(v.y, v.y);
            v = ((const float2*)(g_z + (size_t)r2 * DIM + c * 64))[l];
            Z[2 * 64 + 2 * l] = pack2(v.x, v.x); Z[2 * 64 + 2 * l + 1] = pack2(v.y, v.y);
            v = ((const float2*)(g_z + (size_t)r3 * DIM + c * 64))[l];
            Z[3 * 64 + 2 * l] = pack2(v.x, v.x); Z[3 * 64 + 2 * l + 1] = pack2(v.y, v.y);
        }
        __syncthreads();
        #pragma unroll 8
        for (int k = 0; k < 64; k++) {
            ulonglong2 wa = sW2[k * 64 + l];
            ulonglong2 wb = sW2[k * 64 + 32 + l];
            #pragma unroll
            for (int j = 0; j < 4; j++) {
                ull a = Z[j * 64 + k];
                acc[j][0] = ffma2(a, wa.x, acc[j][0]);
                acc[j][1] = ffma2(a, wa.y, acc[j][1]);
                acc[j][2] = ffma2(a, wb.x, acc[j][2]);
                acc[j][3] = ffma2(a, wb.y, acc[j][3]);
            }
        }
    }

    float4 ba = ((const float4*)b1)[l], bb = ((const float4*)b1)[32 + l];
    #pragma unroll
    for (int j = 0; j < 4; j++) {
        int row = rbase + j;
        if (row < NN) {
            float m0, m1, m2, m3, m4, m5, m6, m7;
            unpack2(acc[j][0], m0, m1); unpack2(acc[j][1], m2, m3);
            unpack2(acc[j][2], m4, m5); unpack2(acc[j][3], m6, m7);
            float4 va = make_float4(fmaxf(m0 + ba.x, 0.f), fmaxf(m1 + ba.y, 0.f),
                                    fmaxf(m2 + ba.z, 0.f), fmaxf(m3 + ba.w, 0.f));
            float4 vb = make_float4(fmaxf(m4 + bb.x, 0.f), fmaxf(m5 + bb.y, 0.f),
                                    fmaxf(m6 + bb.z, 0.f), fmaxf(m7 + bb.w, 0.f));
            ((float4*)(g_h1 + (size_t)row * DIM))[l] = va;
            ((float4*)(g_h1 + (size_t)row * DIM))[32 + l] = vb;
        }
    }
}

// ---------------------------------------------------------------------------
// Kernel 4: out = LayerNorm(relu(h1 @ W2 + b2) + x) * gamma + beta
// Same GEMM structure; epilogue does residual + per-row LN via warp reduction.
// ---------------------------------------------------------------------------
__global__ __launch_bounds__(256) void k_mlp2(
    const float* __restrict__ x, const float* __restrict__ W2,
    const float* __restrict__ b2, const float* __restrict__ gamma,
    const float* __restrict__ beta, float* __restrict__ out)
{
    extern __shared__ char smem[];
    ulonglong2* sW2 = (ulonglong2*)smem;
    float4* sWf = (float4*)smem;
    ull* sZ = (ull*)(smem + 65536);

    int t = threadIdx.x, w = t >> 5, l = t & 31;
    int rbase = blockIdx.x * 32 + w * 4;
    int rc[4];
    #pragma unroll
    for (int j = 0; j < 4; j++) rc[j] = min(rbase + j, NN - 1);

    ull acc[4][4];
    #pragma unroll
    for (int j = 0; j < 4; j++) { acc[j][0] = 0; acc[j][1] = 0; acc[j][2] = 0; acc[j][3] = 0; }

    const float4* Wg = (const float4*)W2;
    ull* Z = sZ + (size_t)w * 4 * 64;

    for (int c = 0; c < 4; c++) {
        __syncthreads();
        #pragma unroll
        for (int i = 0; i < 16; i++) sWf[t + 256 * i] = Wg[c * 4096 + t + 256 * i];
        #pragma unroll
        for (int j = 0; j < 4; j++) {
            float2 v = ((const float2*)(g_h1 + (size_t)rc[j] * DIM + c * 64))[l];
            Z[j * 64 + 2 * l] = pack2(v.x, v.x); Z[j * 64 + 2 * l + 1] = pack2(v.y, v.y);
        }
        __syncthreads();
        #pragma unroll 8
        for (int k = 0; k < 64; k++) {
            ulonglong2 wa = sW2[k * 64 + l];
            ulonglong2 wb = sW2[k * 64 + 32 + l];
            #pragma unroll
            for (int j = 0; j < 4; j++) {
                ull a = Z[j * 64 + k];
                acc[j][0] = ffma2(a, wa.x, acc[j][0]);
                acc[j][1] = ffma2(a, wa.y, acc[j][1]);
                acc[j][2] = ffma2(a, wb.x, acc[j][2]);
                acc[j][3] = ffma2(a, wb.y, acc[j][3]);
            }
        }
    }

    float4 ba  = ((const float4*)b2)[l],    bb  = ((const float4*)b2)[32 + l];
    float4 ga  = ((const float4*)gamma)[l], gb  = ((const float4*)gamma)[32 + l];
    float4 bta = ((const float4*)beta)[l],  btb = ((const float4*)beta)[32 + l];

    #pragma unroll
    for (int j = 0; j < 4; j++) {
        int row = rbase + j;
        const float4* xr = (const float4*)(x + (size_t)rc[j] * DIM);
        float4 xa = xr[l], xb = xr[32 + l];
        float m0, m1, m2, m3, m4, m5, m6, m7;
        unpack2(acc[j][0], m0, m1); unpack2(acc[j][1], m2, m3);
        unpack2(acc[j][2], m4, m5); unpack2(acc[j][3], m6, m7);
        float h0 = fmaxf(m0 + ba.x, 0.f) + xa.x;
        float h1v = fmaxf(m1 + ba.y, 0.f) + xa.y;
        float h2 = fmaxf(m2 + ba.z, 0.f) + xa.z;
        float h3 = fmaxf(m3 + ba.w, 0.f) + xa.w;
        float h4 = fmaxf(m4 + bb.x, 0.f) + xb.x;
        float h5 = fmaxf(m5 + bb.y, 0.f) + xb.y;
        float h6 = fmaxf(m6 + bb.z, 0.f) + xb.z;
        float h7 = fmaxf(m7 + bb.w, 0.f) + xb.w;

        float s = h0 + h1v + h2 + h3 + h4 + h5 + h6 + h7;
        float q = h0*h0 + h1v*h1v + h2*h2 + h3*h3 + h4*h4 + h5*h5 + h6*h6 + h7*h7;
        #pragma unroll
        for (int o = 16; o; o >>= 1) {
            s += __shfl_xor_sync(0xffffffffu, s, o);
            q += __shfl_xor_sync(0xffffffffu, q, o);
        }
        float mu = s * (1.0f / 256.0f);
        float var = q * (1.0f / 256.0f) - mu * mu;
        float inv = rsqrtf(var + 1e-5f);

        if (row < NN) {
            float4 oa = make_float4((h0  - mu) * inv * ga.x + bta.x,
                                    (h1v - mu) * inv * ga.y + bta.y,
                                    (h2  - mu) * inv * ga.z + bta.z,
                                    (h3  - mu) * inv * ga.w + bta.w);
            float4 ob = make_float4((h4 - mu) * inv * gb.x + btb.x,
                                    (h5 - mu) * inv * gb.y + btb.y,
                                    (h6 - mu) * inv * gb.z + btb.z,
                                    (h7 - mu) * inv * gb.w + btb.w);
            ((float4*)(out + (size_t)row * DIM))[l] = oa;
            ((float4*)(out + (size_t)row * DIM))[32 + l] = ob;
        }
    }
}

// ---------------------------------------------------------------------------
extern "C" void kernel_launch(void* const* d_in, const int* in_sizes, int n_in,
                              void* d_out, int out_size)
{
    const float* x     = (const float*)d_in[0];
    const int*   eidx  = (const int*)d_in[1];     // int32 (JAX x64 disabled)
    const float* ea    = (const float*)d_in[2];
    const float* We    = (const float*)d_in[3];
    const float* be    = (const float*)d_in[4];
    const float* W1    = (const float*)d_in[5];
    const float* b1    = (const float*)d_in[6];
    const float* W2    = (const float*)d_in[7];
    const float* b2    = (const float*)d_in[8];
    const float* gamma = (const float*)d_in[9];
    const float* beta  = (const float*)d_in[10];
    float* out         = (float*)d_out;

    cudaFuncSetAttribute(k_edge, cudaFuncAttributeMaxDynamicSharedMemorySize, 73728);
    cudaFuncSetAttribute(k_mlp1, cudaFuncAttributeMaxDynamicSharedMemorySize, 81920);
    cudaFuncSetAttribute(k_mlp2, cudaFuncAttributeMaxDynamicSharedMemorySize, 81920);

    k_init<<<12500, 256>>>((const float4*)x);
    k_edge<<<6250, 256, 73728>>>(x, eidx, ea, We, be);
    k_mlp1<<<1563, 256, 81920>>>(W1, b1);
    k_mlp2<<<1563, 256, 81920>>>(x, W2, b2, gamma, beta, out);
}

// round 3
// speedup vs baseline: 1.1822x; 1.1822x over previous
#include <cuda_runtime.h>

#define NN 50000
#define NE 800000
#define DIM 256
#define EDIM 64

typedef unsigned long long ull;

// Scratch (static __device__ — no runtime allocation)
__device__ __align__(16) float g_z[NN * DIM];   // z = x + aggr (atomic target)
__device__ __align__(16) float g_h1[NN * DIM];  // hidden after MLP layer 1

__device__ __forceinline__ ull pack2(float x, float y) {
    ull r; asm("mov.b64 %0, {%1,%2};" : "=l"(r) : "f"(x), "f"(y)); return r;
}
__device__ __forceinline__ void unpack2(ull v, float& x, float& y) {
    asm("mov.b64 {%0,%1}, %2;" : "=f"(x), "=f"(y) : "l"(v));
}
// Packed fp32x2 FMA (Blackwell)
__device__ __forceinline__ ull ffma2(ull a, ull b, ull c) {
    ull d; asm("fma.rn.f32x2 %0, %1, %2, %3;" : "=l"(d) : "l"(a), "l"(b), "l"(c)); return d;
}
// Vector reduction atomic (sm_90+): 4 floats, no return
__device__ __forceinline__ void red4(float* a, float4 v) {
    asm volatile("red.global.add.v4.f32 [%0], {%1,%2,%3,%4};"
                 :: "l"(a), "f"(v.x), "f"(v.y), "f"(v.z), "f"(v.w));
}

// ---------------------------------------------------------------------------
// Kernel 1: z = x
// ---------------------------------------------------------------------------
__global__ __launch_bounds__(256) void k_init(const float4* __restrict__ x) {
    int i = blockIdx.x * 256 + threadIdx.x;
    reinterpret_cast<float4*>(g_z)[i] = x[i];
}

// ---------------------------------------------------------------------------
// Kernel 2: per-edge  msg = relu(x[src] + edge_attr@We + be); red.v4 into g_z[dst]
// Block = 256 threads (8 warps); warp processes 16 edges in 2 batches of 8.
// 8 edges share each W smem load -> FMA-bound instead of LDS-bound.
// ---------------------------------------------------------------------------
__global__ __launch_bounds__(256) void k_edge(
    const float* __restrict__ x, const int* __restrict__ eidx,
    const float* __restrict__ ea, const float* __restrict__ We,
    const float* __restrict__ be)
{
    extern __shared__ char smem[];
    ulonglong2* sW2 = (ulonglong2*)smem;            // [64 k][64 pairs] (64 KB)
    ull* sA = (ull*)(smem + 65536);                 // [8 warps][8 edges][64] packed-dup (32 KB)

    int t = threadIdx.x, w = t >> 5, l = t & 31;

    {   // stage We: 4096 float4s
        const float4* We4 = (const float4*)We;
        float4* sWf = (float4*)smem;
        #pragma unroll
        for (int i = 0; i < 16; i++) sWf[t + 256 * i] = We4[t + 256 * i];
    }
    float4 beA = ((const float4*)be)[l];
    float4 beB = ((const float4*)be)[32 + l];
    __syncthreads();

    ull* A = sA + (size_t)w * 512;
    long long ebase = (long long)blockIdx.x * 128 + (long long)w * 16;

    #pragma unroll 1
    for (int half = 0; half < 2; half++) {
        long long e0 = ebase + half * 8;
        __syncwarp();
        #pragma unroll
        for (int e = 0; e < 8; e++) {
            float2 a = ((const float2*)(ea + (e0 + e) * EDIM))[l];
            A[e * 64 + 2 * l]     = pack2(a.x, a.x);
            A[e * 64 + 2 * l + 1] = pack2(a.y, a.y);
        }
        __syncwarp();

        ull acc[8][4];
        #pragma unroll
        for (int e = 0; e < 8; e++) { acc[e][0] = 0; acc[e][1] = 0; acc[e][2] = 0; acc[e][3] = 0; }

        #pragma unroll 4
        for (int k = 0; k < EDIM; k++) {
            ulonglong2 wa = sW2[k * 64 + l];
            ulonglong2 wb = sW2[k * 64 + 32 + l];
            #pragma unroll
            for (int e = 0; e < 8; e++) {
                ull a = A[e * 64 + k];
                acc[e][0] = ffma2(a, wa.x, acc[e][0]);
                acc[e][1] = ffma2(a, wa.y, acc[e][1]);
                acc[e][2] = ffma2(a, wb.x, acc[e][2]);
                acc[e][3] = ffma2(a, wb.y, acc[e][3]);
            }
        }

        #pragma unroll 1
        for (int e = 0; e < 8; e++) {
            long long s = eidx[e0 + e], d = eidx[NE + e0 + e];
            const float4* xr = (const float4*)(x + s * DIM);
            float4 xa = xr[l], xb = xr[32 + l];
            float m0, m1, m2, m3, m4, m5, m6, m7;
            unpack2(acc[e][0], m0, m1); unpack2(acc[e][1], m2, m3);
            unpack2(acc[e][2], m4, m5); unpack2(acc[e][3], m6, m7);
            float4 va = make_float4(fmaxf(m0 + xa.x + beA.x, 0.f), fmaxf(m1 + xa.y + beA.y, 0.f),
                                    fmaxf(m2 + xa.z + beA.z, 0.f), fmaxf(m3 + xa.w + beA.w, 0.f));
            float4 vb = make_float4(fmaxf(m4 + xb.x + beB.x, 0.f), fmaxf(m5 + xb.y + beB.y, 0.f),
                                    fmaxf(m6 + xb.z + beB.z, 0.f), fmaxf(m7 + xb.w + beB.w, 0.f));
            red4(g_z + d * DIM + 4 * l, va);
            red4(g_z + d * DIM + 128 + 4 * l, vb);
        }
    }
}

// ---------------------------------------------------------------------------
// Kernel 3: h1 = relu(z @ W1 + b1)   [NN,256] @ [256,256]
// Warp handles 8 rows; K tiled in 4 chunks of 64 (W chunk in smem).
// ---------------------------------------------------------------------------
__global__ __launch_bounds__(256) void k_mlp1(const float* __restrict__ W1,
                                              const float* __restrict__ b1)
{
    extern __shared__ char smem[];
    ulonglong2* sW2 = (ulonglong2*)smem;   // 64 KB chunk of W
    float4* sWf = (float4*)smem;
    ull* sZ = (ull*)(smem + 65536);        // [8 warps][8 rows][64] packed-dup (32 KB)

    int t = threadIdx.x, w = t >> 5, l = t & 31;
    int rbase = blockIdx.x * 64 + w * 8;
    int rc[8];
    #pragma unroll
    for (int j = 0; j < 8; j++) rc[j] = min(rbase + j, NN - 1);

    ull acc[8][4];
    #pragma unroll
    for (int j = 0; j < 8; j++) { acc[j][0] = 0; acc[j][1] = 0; acc[j][2] = 0; acc[j][3] = 0; }

    const float4* Wg = (const float4*)W1;
    ull* Z = sZ + (size_t)w * 512;

    #pragma unroll 1
    for (int c = 0; c < 4; c++) {
        __syncthreads();
        #pragma unroll
        for (int i = 0; i < 16; i++) sWf[t + 256 * i] = Wg[c * 4096 + t + 256 * i];
        #pragma unroll
        for (int j = 0; j < 8; j++) {
            float2 v = ((const float2*)(g_z + (size_t)rc[j] * DIM + c * 64))[l];
            Z[j * 64 + 2 * l]     = pack2(v.x, v.x);
            Z[j * 64 + 2 * l + 1] = pack2(v.y, v.y);
        }
        __syncthreads();
        #pragma unroll 4
        for (int k = 0; k < 64; k++) {
            ulonglong2 wa = sW2[k * 64 + l];
            ulonglong2 wb = sW2[k * 64 + 32 + l];
            #pragma unroll
            for (int j = 0; j < 8; j++) {
                ull a = Z[j * 64 + k];
                acc[j][0] = ffma2(a, wa.x, acc[j][0]);
                acc[j][1] = ffma2(a, wa.y, acc[j][1]);
                acc[j][2] = ffma2(a, wb.x, acc[j][2]);
                acc[j][3] = ffma2(a, wb.y, acc[j][3]);
            }
        }
    }

    float4 ba = ((const float4*)b1)[l], bb = ((const float4*)b1)[32 + l];
    #pragma unroll 1
    for (int j = 0; j < 8; j++) {
        int row = rbase + j;
        if (row < NN) {
            float m0, m1, m2, m3, m4, m5, m6, m7;
            unpack2(acc[j][0], m0, m1); unpack2(acc[j][1], m2, m3);
            unpack2(acc[j][2], m4, m5); unpack2(acc[j][3], m6, m7);
            float4 va = make_float4(fmaxf(m0 + ba.x, 0.f), fmaxf(m1 + ba.y, 0.f),
                                    fmaxf(m2 + ba.z, 0.f), fmaxf(m3 + ba.w, 0.f));
            float4 vb = make_float4(fmaxf(m4 + bb.x, 0.f), fmaxf(m5 + bb.y, 0.f),
                                    fmaxf(m6 + bb.z, 0.f), fmaxf(m7 + bb.w, 0.f));
            ((float4*)(g_h1 + (size_t)row * DIM))[l] = va;
            ((float4*)(g_h1 + (size_t)row * DIM))[32 + l] = vb;
        }
    }
}

// ---------------------------------------------------------------------------
// Kernel 4: out = LayerNorm(relu(h1 @ W2 + b2) + x) * gamma + beta
// ---------------------------------------------------------------------------
__global__ __launch_bounds__(256) void k_mlp2(
    const float* __restrict__ x, const float* __restrict__ W2,
    const float* __restrict__ b2, const float* __restrict__ gamma,
    const float* __restrict__ beta, float* __restrict__ out)
{
    extern __shared__ char smem[];
    ulonglong2* sW2 = (ulonglong2*)smem;
    float4* sWf = (float4*)smem;
    ull* sZ = (ull*)(smem + 65536);

    int t = threadIdx.x, w = t >> 5, l = t & 31;
    int rbase = blockIdx.x * 64 + w * 8;
    int rc[8];
    #pragma unroll
    for (int j = 0; j < 8; j++) rc[j] = min(rbase + j, NN - 1);

    ull acc[8][4];
    #pragma unroll
    for (int j = 0; j < 8; j++) { acc[j][0] = 0; acc[j][1] = 0; acc[j][2] = 0; acc[j][3] = 0; }

    const float4* Wg = (const float4*)W2;
    ull* Z = sZ + (size_t)w * 512;

    #pragma unroll 1
    for (int c = 0; c < 4; c++) {
        __syncthreads();
        #pragma unroll
        for (int i = 0; i < 16; i++) sWf[t + 256 * i] = Wg[c * 4096 + t + 256 * i];
        #pragma unroll
        for (int j = 0; j < 8; j++) {
            float2 v = ((const float2*)(g_h1 + (size_t)rc[j] * DIM + c * 64))[l];
            Z[j * 64 + 2 * l]     = pack2(v.x, v.x);
            Z[j * 64 + 2 * l + 1] = pack2(v.y, v.y);
        }
        __syncthreads();
        #pragma unroll 4
        for (int k = 0; k < 64; k++) {
            ulonglong2 wa = sW2[k * 64 + l];
            ulonglong2 wb = sW2[k * 64 + 32 + l];
            #pragma unroll
            for (int j = 0; j < 8; j++) {
                ull a = Z[j * 64 + k];
                acc[j][0] = ffma2(a, wa.x, acc[j][0]);
                acc[j][1] = ffma2(a, wa.y, acc[j][1]);
                acc[j][2] = ffma2(a, wb.x, acc[j][2]);
                acc[j][3] = ffma2(a, wb.y, acc[j][3]);
            }
        }
    }

    float4 ba  = ((const float4*)b2)[l],    bb  = ((const float4*)b2)[32 + l];
    float4 ga  = ((const float4*)gamma)[l], gb  = ((const float4*)gamma)[32 + l];
    float4 bta = ((const float4*)beta)[l],  btb = ((const float4*)beta)[32 + l];

    #pragma unroll 1
    for (int j = 0; j < 8; j++) {
        int row = rbase + j;
        const float4* xr = (const float4*)(x + (size_t)rc[j] * DIM);
        float4 xa = xr[l], xb = xr[32 + l];
        float m0, m1, m2, m3, m4, m5, m6, m7;
        unpack2(acc[j][0], m0, m1); unpack2(acc[j][1], m2, m3);
        unpack2(acc[j][2], m4, m5); unpack2(acc[j][3], m6, m7);
        float h0 = fmaxf(m0 + ba.x, 0.f) + xa.x;
        float h1v = fmaxf(m1 + ba.y, 0.f) + xa.y;
        float h2 = fmaxf(m2 + ba.z, 0.f) + xa.z;
        float h3 = fmaxf(m3 + ba.w, 0.f) + xa.w;
        float h4 = fmaxf(m4 + bb.x, 0.f) + xb.x;
        float h5 = fmaxf(m5 + bb.y, 0.f) + xb.y;
        float h6 = fmaxf(m6 + bb.z, 0.f) + xb.z;
        float h7 = fmaxf(m7 + bb.w, 0.f) + xb.w;

        float s = h0 + h1v + h2 + h3 + h4 + h5 + h6 + h7;
        float q = h0*h0 + h1v*h1v + h2*h2 + h3*h3 + h4*h4 + h5*h5 + h6*h6 + h7*h7;
        #pragma unroll
        for (int o = 16; o; o >>= 1) {
            s += __shfl_xor_sync(0xffffffffu, s, o);
            q += __shfl_xor_sync(0xffffffffu, q, o);
        }
        float mu = s * (1.0f / 256.0f);
        float var = q * (1.0f / 256.0f) - mu * mu;
        float inv = rsqrtf(var + 1e-5f);

        if (row < NN) {
            float4 oa = make_float4((h0  - mu) * inv * ga.x + bta.x,
                                    (h1v - mu) * inv * ga.y + bta.y,
                                    (h2  - mu) * inv * ga.z + bta.z,
                                    (h3  - mu) * inv * ga.w + bta.w);
            float4 ob = make_float4((h4 - mu) * inv * gb.x + btb.x,
                                    (h5 - mu) * inv * gb.y + btb.y,
                                    (h6 - mu) * inv * gb.z + btb.z,
                                    (h7 - mu) * inv * gb.w + btb.w);
            ((float4*)(out + (size_t)row * DIM))[l] = oa;
            ((float4*)(out + (size_t)row * DIM))[32 + l] = ob;
        }
    }
}

// ---------------------------------------------------------------------------
extern "C" void kernel_launch(void* const* d_in, const int* in_sizes, int n_in,
                              void* d_out, int out_size)
{
    const float* x     = (const float*)d_in[0];
    const int*   eidx  = (const int*)d_in[1];     // int32 (JAX x64 disabled)
    const float* ea    = (const float*)d_in[2];
    const float* We    = (const float*)d_in[3];
    const float* be    = (const float*)d_in[4];
    const float* W1    = (const float*)d_in[5];
    const float* b1    = (const float*)d_in[6];
    const float* W2    = (const float*)d_in[7];
    const float* b2    = (const float*)d_in[8];
    const float* gamma = (const float*)d_in[9];
    const float* beta  = (const float*)d_in[10];
    float* out         = (float*)d_out;

    cudaFuncSetAttribute(k_edge, cudaFuncAttributeMaxDynamicSharedMemorySize, 98304);
    cudaFuncSetAttribute(k_mlp1, cudaFuncAttributeMaxDynamicSharedMemorySize, 98304);
    cudaFuncSetAttribute(k_mlp2, cudaFuncAttributeMaxDynamicSharedMemorySize, 98304);

    k_init<<<12500, 256>>>((const float4*)x);
    k_edge<<<6250, 256, 98304>>>(x, eidx, ea, We, be);
    k_mlp1<<<782, 256, 98304>>>(W1, b1);
    k_mlp2<<<782, 256, 98304>>>(x, W2, b2, gamma, beta, out);
}

// round 5
// speedup vs baseline: 1.2875x; 1.0891x over previous
#include <cuda_runtime.h>
#include <cuda_bf16.h>
#include <cstdint>

#define NN 50000
#define NE 800000
#define DIM 256

__device__ __align__(16) float g_z[NN * DIM];   // z = x + aggr; later pre-LN h
__device__ __align__(16) float g_h1[NN * DIM];  // hidden after MLP layer 1

template <int S>
__device__ __forceinline__ uint32_t swz(uint32_t off) {
    return off ^ (((off >> S) & 7u) << 4);
}
__device__ __forceinline__ uint32_t smem_u32(const void* p) {
    uint32_t a;
    asm("{ .reg .u64 t; cvta.to.shared.u64 t, %1; cvt.u32.u64 %0, t; }" : "=r"(a) : "l"(p));
    return a;
}
__device__ __forceinline__ void ldsm4(uint32_t r[4], uint32_t a) {
    asm volatile("ldmatrix.sync.aligned.m8n8.x4.shared.b16 {%0,%1,%2,%3}, [%4];"
                 : "=r"(r[0]), "=r"(r[1]), "=r"(r[2]), "=r"(r[3]) : "r"(a));
}
__device__ __forceinline__ void ldsm4t(uint32_t r[4], uint32_t a) {
    asm volatile("ldmatrix.sync.aligned.m8n8.x4.trans.shared.b16 {%0,%1,%2,%3}, [%4];"
                 : "=r"(r[0]), "=r"(r[1]), "=r"(r[2]), "=r"(r[3]) : "r"(a));
}
__device__ __forceinline__ void mma16816(float d[4], const uint32_t a[4], const uint32_t b[2]) {
    asm volatile("mma.sync.aligned.m16n8k16.row.col.f32.bf16.bf16.f32 "
                 "{%0,%1,%2,%3}, {%4,%5,%6,%7}, {%8,%9}, {%0,%1,%2,%3};"
                 : "+f"(d[0]), "+f"(d[1]), "+f"(d[2]), "+f"(d[3])
                 : "r"(a[0]), "r"(a[1]), "r"(a[2]), "r"(a[3]), "r"(b[0]), "r"(b[1]));
}
__device__ __forceinline__ void red4(float* a, float4 v) {
    asm volatile("red.global.add.v4.f32 [%0], {%1,%2,%3,%4};"
                 :: "l"(a), "f"(v.x), "f"(v.y), "f"(v.z), "f"(v.w));
}
// Split float pair into bf16 hi + bf16 residual, store both to swizzled smem
__device__ __forceinline__ void pack_pair(char* hiB, char* loB, uint32_t sw, float2 v) {
    __nv_bfloat16 h0 = __float2bfloat16(v.x), h1 = __float2bfloat16(v.y);
    __nv_bfloat16 l0 = __float2bfloat16(v.x - __bfloat162float(h0));
    __nv_bfloat16 l1 = __float2bfloat16(v.y - __bfloat162float(h1));
    *(__nv_bfloat162*)(hiB + sw) = __halves2bfloat162(h0, h1);
    *(__nv_bfloat162*)(loB + sw) = __halves2bfloat162(l0, l1);
}

// ---------------------------------------------------------------------------
// Core: accumulate 128x128 half-tile over a staged 64-k chunk.
// A: [128 m][64 k] bf16 hi/lo, 128B rows, swz<7>.  B: [64 k][128 n] bf16 hi/lo,
// 256B rows, swz<8>.  3 passes: Ah*Bh + Ah*Bl + Al*Bh.
// Warp (wm = w&3, wn = w>>2) owns rows [wm*32, +32), cols [wn*64, +64).
// ---------------------------------------------------------------------------
__device__ __forceinline__ void mma_chunk(float acc[2][8][4],
    uint32_t aHi, uint32_t aLo, uint32_t bHi, uint32_t bLo, int wm, int wn, int l)
{
    const int lr = l & 7, lg8 = ((l >> 3) & 1) * 8, lh8 = (l >> 4) * 8;
    #pragma unroll
    for (int pass = 0; pass < 3; pass++) {
        const uint32_t Ab = (pass == 2) ? aLo : aHi;
        const uint32_t Bb = (pass == 1) ? bLo : bHi;
        #pragma unroll
        for (int ks = 0; ks < 4; ks++) {
            uint32_t a[2][4];
            #pragma unroll
            for (int mf = 0; mf < 2; mf++) {
                uint32_t off = (uint32_t)((wm * 32 + mf * 16 + lr + lg8) * 128
                                          + (ks * 16 + lh8) * 2);
                ldsm4(a[mf], Ab + swz<7>(off));
            }
            uint32_t b[8][2];
            #pragma unroll
            for (int nq = 0; nq < 4; nq++) {
                uint32_t off = (uint32_t)((ks * 16 + lr + lg8) * 256
                                          + (wn * 64 + nq * 16 + lh8) * 2);
                uint32_t r4[4];
                ldsm4t(r4, Bb + swz<8>(off));
                b[2 * nq][0] = r4[0]; b[2 * nq][1] = r4[1];
                b[2 * nq + 1][0] = r4[2]; b[2 * nq + 1][1] = r4[3];
            }
            #pragma unroll
            for (int mf = 0; mf < 2; mf++)
                #pragma unroll
                for (int nf = 0; nf < 8; nf++)
                    mma16816(acc[mf][nf], a[mf], b[nf]);
        }
    }
}

// ---------------------------------------------------------------------------
// Kernel 1: z = x
// ---------------------------------------------------------------------------
__global__ __launch_bounds__(256) void k_init(const float4* __restrict__ x) {
    int i = blockIdx.x * 256 + threadIdx.x;
    reinterpret_cast<float4*>(g_z)[i] = x[i];
}

// ---------------------------------------------------------------------------
// Kernel 2: edge GEMM + scatter. CTA = 128 edges.
// msg = relu(edge_attr@We + x[src] + be) -> red.v4 into g_z[dst].
// ---------------------------------------------------------------------------
#define E_BE  0
#define E_AH  1024
#define E_AL  17408
#define E_BH  33792
#define E_BL  50176
#define E_SCR 66560
#define E_SMEM 101376   // E_SCR + 128*272

__global__ __launch_bounds__(256, 2) void k_edge(
    const float* __restrict__ x, const int* __restrict__ eidx,
    const float* __restrict__ ea, const float* __restrict__ We,
    const float* __restrict__ be)
{
    extern __shared__ char sm[];
    const int t = threadIdx.x, w = t >> 5, l = t & 31;
    const int wm = w & 3, wn = w >> 2;
    const uint32_t sb = smem_u32(sm);

    if (t < 64) ((float4*)(sm + E_BE))[t] = ((const float4*)be)[t];

    // Stage A = edge_attr [128][64] hi/lo
    const float2* ea2 = (const float2*)(ea + (size_t)blockIdx.x * (128 * 64));
    #pragma unroll
    for (int i0 = 0; i0 < 16; i0++) {
        int i = i0 * 256 + t;
        int r = i >> 5, kp = i & 31;
        pack_pair(sm + E_AH, sm + E_AL, swz<7>((uint32_t)(r * 128 + kp * 4)), ea2[i]);
    }

    const int erow = t >> 1, part = t & 1;
    const long long eb = (long long)blockIdx.x * 128 + erow;
    const int si = eidx[eb], di = eidx[NE + eb];
    const float4* xs = (const float4*)(x + (size_t)si * DIM);
    float* zd = g_z + (size_t)di * DIM;
    const float4* bes = (const float4*)(sm + E_BE);

    #pragma unroll 1
    for (int hf = 0; hf < 2; hf++) {
        __syncthreads();   // prior readers of B / scatter done
        // Stage B-half = We[k][n-half] as [64][128] hi/lo
        const float2* w2 = (const float2*)We;
        #pragma unroll
        for (int i0 = 0; i0 < 16; i0++) {
            int i = i0 * 256 + t;
            int k = i >> 6, np = i & 63;
            pack_pair(sm + E_BH, sm + E_BL, swz<8>((uint32_t)(k * 256 + np * 4)),
                      w2[k * 128 + hf * 64 + np]);
        }
        __syncthreads();

        float acc[2][8][4];
        #pragma unroll
        for (int mf = 0; mf < 2; mf++)
            #pragma unroll
            for (int nf = 0; nf < 8; nf++) {
                acc[mf][nf][0] = 0.f; acc[mf][nf][1] = 0.f;
                acc[mf][nf][2] = 0.f; acc[mf][nf][3] = 0.f;
            }
        mma_chunk(acc, sb + E_AH, sb + E_AL, sb + E_BH, sb + E_BL, wm, wn, l);

        // Epilogue: per n-quarter, transpose through scratch, then red.v4
        #pragma unroll 1
        for (int q = 0; q < 2; q++) {
            __syncthreads();
            if (wn == q) {
                #pragma unroll
                for (int mf = 0; mf < 2; mf++)
                    #pragma unroll
                    for (int nf = 0; nf < 8; nf++) {
                        int r0 = wm * 32 + mf * 16 + (l >> 2);
                        int cb = nf * 8 + 2 * (l & 3);
                        *(float2*)(sm + E_SCR + r0 * 272 + cb * 4) =
                            make_float2(acc[mf][nf][0], acc[mf][nf][1]);
                        *(float2*)(sm + E_SCR + (r0 + 8) * 272 + cb * 4) =
                            make_float2(acc[mf][nf][2], acc[mf][nf][3]);
                    }
            }
            __syncthreads();
            const int gbase = hf * 32 + q * 16;   // float4 index base in row
            #pragma unroll
            for (int j = 0; j < 8; j++) {
                int cj = 2 * j + part;            // float4 chunk within 64 cols
                float4 v = *(const float4*)(sm + E_SCR + erow * 272 + cj * 16);
                float4 xv = xs[gbase + cj];
                float4 bv = bes[gbase + cj];
                float4 o;
                o.x = fmaxf(v.x + xv.x + bv.x, 0.f);
                o.y = fmaxf(v.y + xv.y + bv.y, 0.f);
                o.z = fmaxf(v.z + xv.z + bv.z, 0.f);
                o.w = fmaxf(v.w + xv.w + bv.w, 0.f);
                red4(zd + (gbase + cj) * 4, o);
            }
        }
    }
}

// ---------------------------------------------------------------------------
// MLP mainloop: accumulate [128 rows x 128 half-cols] = Ain[rows][256] @ W
// ---------------------------------------------------------------------------
#define M_BIAS 0
#define M_AH   1024
#define M_AL   17408
#define M_BH   33792
#define M_BL   50176
#define M_SMEM 66560

__device__ __forceinline__ void mlp_accum_half(float acc[2][8][4],
    const float* __restrict__ Ain, const float* __restrict__ W,
    char* sm, uint32_t sb, int rowb, int hf, int t, int wm, int wn, int l)
{
    #pragma unroll 1
    for (int kc = 0; kc < 4; kc++) {
        __syncthreads();
        const float2* A2 = (const float2*)Ain;
        #pragma unroll
        for (int i0 = 0; i0 < 16; i0++) {
            int i = i0 * 256 + t;
            int r = i >> 5, kp = i & 31;
            int row = min(rowb + r, NN - 1);
            pack_pair(sm + M_AH, sm + M_AL, swz<7>((uint32_t)(r * 128 + kp * 4)),
                      A2[(size_t)row * 128 + kc * 32 + kp]);
        }
        const float2* W2 = (const float2*)W;
        #pragma unroll
        for (int i0 = 0; i0 < 16; i0++) {
            int i = i0 * 256 + t;
            int k = i >> 6, np = i & 63;
            pack_pair(sm + M_BH, sm + M_BL, swz<8>((uint32_t)(k * 256 + np * 4)),
                      W2[(size_t)(kc * 64 + k) * 128 + hf * 64 + np]);
        }
        __syncthreads();
        mma_chunk(acc, sb + M_AH, sb + M_AL, sb + M_BH, sb + M_BL, wm, wn, l);
    }
}

// Kernel 3: h1 = relu(z @ W1 + b1) -> g_h1
__global__ __launch_bounds__(256, 2) void k_mlp1(const float* __restrict__ W1,
                                                 const float* __restrict__ b1)
{
    extern __shared__ char sm[];
    const int t = threadIdx.x, w = t >> 5, l = t & 31;
    const int wm = w & 3, wn = w >> 2;
    const uint32_t sb = smem_u32(sm);
    if (t < 64) ((float4*)(sm + M_BIAS))[t] = ((const float4*)b1)[t];
    const int rowb = blockIdx.x * 128;

    #pragma unroll 1
    for (int hf = 0; hf < 2; hf++) {
        float acc[2][8][4];
        #pragma unroll
        for (int mf = 0; mf < 2; mf++)
            #pragma unroll
            for (int nf = 0; nf < 8; nf++) {
                acc[mf][nf][0] = 0.f; acc[mf][nf][1] = 0.f;
                acc[mf][nf][2] = 0.f; acc[mf][nf][3] = 0.f;
            }
        mlp_accum_half(acc, g_z, W1, sm, sb, rowb, hf, t, wm, wn, l);

        #pragma unroll
        for (int mf = 0; mf < 2; mf++)
            #pragma unroll
            for (int nf = 0; nf < 8; nf++) {
                int col = hf * 128 + wn * 64 + nf * 8 + 2 * (l & 3);
                float2 bb = *(const float2*)(sm + M_BIAS + col * 4);
                int r = rowb + wm * 32 + mf * 16 + (l >> 2);
                if (r < NN)
                    *(float2*)(g_h1 + (size_t)r * DIM + col) =
                        make_float2(fmaxf(acc[mf][nf][0] + bb.x, 0.f),
                                    fmaxf(acc[mf][nf][1] + bb.y, 0.f));
                if (r + 8 < NN)
                    *(float2*)(g_h1 + (size_t)(r + 8) * DIM + col) =
                        make_float2(fmaxf(acc[mf][nf][2] + bb.x, 0.f),
                                    fmaxf(acc[mf][nf][3] + bb.y, 0.f));
            }
    }
}

// Kernel 4: h = relu(h1 @ W2 + b2) + x -> g_z (pre-LN)
__global__ __launch_bounds__(256, 2) void k_mlp2(const float* __restrict__ x,
                                                 const float* __restrict__ W2,
                                                 const float* __restrict__ b2)
{
    extern __shared__ char sm[];
    const int t = threadIdx.x, w = t >> 5, l = t & 31;
    const int wm = w & 3, wn = w >> 2;
    const uint32_t sb = smem_u32(sm);
    if (t < 64) ((float4*)(sm + M_BIAS))[t] = ((const float4*)b2)[t];
    const int rowb = blockIdx.x * 128;

    #pragma unroll 1
    for (int hf = 0; hf < 2; hf++) {
        float acc[2][8][4];
        #pragma unroll
        for (int mf = 0; mf < 2; mf++)
            #pragma unroll
            for (int nf = 0; nf < 8; nf++) {
                acc[mf][nf][0] = 0.f; acc[mf][nf][1] = 0.f;
                acc[mf][nf][2] = 0.f; acc[mf][nf][3] = 0.f;
            }
        mlp_accum_half(acc, g_h1, W2, sm, sb, rowb, hf, t, wm, wn, l);

        #pragma unroll
        for (int mf = 0; mf < 2; mf++)
            #pragma unroll
            for (int nf = 0; nf < 8; nf++) {
                int col = hf * 128 + wn * 64 + nf * 8 + 2 * (l & 3);
                float2 bb = *(const float2*)(sm + M_BIAS + col * 4);
                int r = rowb + wm * 32 + mf * 16 + (l >> 2);
                if (r < NN) {
                    float2 xv = *(const float2*)(x + (size_t)r * DIM + col);
                    *(float2*)(g_z + (size_t)r * DIM + col) =
                        make_float2(fmaxf(acc[mf][nf][0] + bb.x, 0.f) + xv.x,
                                    fmaxf(acc[mf][nf][1] + bb.y, 0.f) + xv.y);
                }
                if (r + 8 < NN) {
                    float2 xv = *(const float2*)(x + (size_t)(r + 8) * DIM + col);
                    *(float2*)(g_z + (size_t)(r + 8) * DIM + col) =
                        make_float2(fmaxf(acc[mf][nf][2] + bb.x, 0.f) + xv.x,
                                    fmaxf(acc[mf][nf][3] + bb.y, 0.f) + xv.y);
                }
            }
    }
}

// Kernel 5: out = LayerNorm(g_z) * gamma + beta    (warp per row)
__global__ __launch_bounds__(256) void k_ln(const float* __restrict__ gamma,
                                            const float* __restrict__ beta,
                                            float* __restrict__ out)
{
    const int w = threadIdx.x >> 5, l = threadIdx.x & 31;
    const int row = blockIdx.x * 8 + w;
    const float4* hr = (const float4*)(g_z + (size_t)row * DIM);
    float4 v0 = hr[l], v1 = hr[32 + l];
    float s = v0.x + v0.y + v0.z + v0.w + v1.x + v1.y + v1.z + v1.w;
    float q = v0.x * v0.x + v0.y * v0.y + v0.z * v0.z + v0.w * v0.w
            + v1.x * v1.x + v1.y * v1.y + v1.z * v1.z + v1.w * v1.w;
    #pragma unroll
    for (int o = 16; o; o >>= 1) {
        s += __shfl_xor_sync(0xffffffffu, s, o);
        q += __shfl_xor_sync(0xffffffffu, q, o);
    }
    float mu = s * (1.0f / 256.0f);
    float var = q * (1.0f / 256.0f) - mu * mu;
    float inv = rsqrtf(var + 1e-5f);
    float4 ga = ((const float4*)gamma)[l], gb = ((const float4*)gamma)[32 + l];
    float4 ba = ((const float4*)beta)[l],  bb = ((const float4*)beta)[32 + l];
    float4 o0, o1;
    o0.x = (v0.x - mu) * inv * ga.x + ba.x;
    o0.y = (v0.y - mu) * inv * ga.y + ba.y;
    o0.z = (v0.z - mu) * inv * ga.z + ba.z;
    o0.w = (v0.w - mu) * inv * ga.w + ba.w;
    o1.x = (v1.x - mu) * inv * gb.x + bb.x;
    o1.y = (v1.y - mu) * inv * gb.y + bb.y;
    o1.z = (v1.z - mu) * inv * gb.z + bb.z;
    o1.w = (v1.w - mu) * inv * gb.w + bb.w;
    ((float4*)(out + (size_t)row * DIM))[l] = o0;
    ((float4*)(out + (size_t)row * DIM))[32 + l] = o1;
}

// ---------------------------------------------------------------------------
extern "C" void kernel_launch(void* const* d_in, const int* in_sizes, int n_in,
                              void* d_out, int out_size)
{
    const float* x     = (const float*)d_in[0];
    const int*   eidx  = (const int*)d_in[1];     // int32 (JAX x64 disabled)
    const float* ea    = (const float*)d_in[2];
    const float* We    = (const float*)d_in[3];
    const float* be    = (const float*)d_in[4];
    const float* W1    = (const float*)d_in[5];
    const float* b1    = (const float*)d_in[6];
    const float* W2    = (const float*)d_in[7];
    const float* b2    = (const float*)d_in[8];
    const float* gamma = (const float*)d_in[9];
    const float* beta  = (const float*)d_in[10];
    float* out         = (float*)d_out;

    cudaFuncSetAttribute(k_edge, cudaFuncAttributeMaxDynamicSharedMemorySize, E_SMEM);
    cudaFuncSetAttribute(k_mlp1, cudaFuncAttributeMaxDynamicSharedMemorySize, M_SMEM);
    cudaFuncSetAttribute(k_mlp2, cudaFuncAttributeMaxDynamicSharedMemorySize, M_SMEM);

    k_init<<<12500, 256>>>((const float4*)x);
    k_edge<<<6250, 256, E_SMEM>>>(x, eidx, ea, We, be);
    k_mlp1<<<391, 256, M_SMEM>>>(W1, b1);
    k_mlp2<<<391, 256, M_SMEM>>>(x, W2, b2);
    k_ln<<<6250, 256>>>(gamma, beta, out);
}

// round 6
// speedup vs baseline: 2.8971x; 2.2502x over previous
#include <cuda_runtime.h>
#include <cuda_bf16.h>
#include <cstdint>

#define NN 50000
#define NE 800000
#define DIM 256
#define RB 391   // ceil(NN/128)

typedef unsigned long long ull;

// ---------------- global scratch ----------------
__device__ __align__(16) float g_z[NN * DIM];          // z = x + aggr; later pre-LN h
__device__ __align__(128) char g_weH[32768];           // We image  [64k][256n] bf16 hi
__device__ __align__(128) char g_weL[32768];
__device__ __align__(128) char g_w1H[131072];          // W1 images, 4 chunks x 32KB
__device__ __align__(128) char g_w1L[131072];
__device__ __align__(128) char g_w2H[131072];
__device__ __align__(128) char g_w2L[131072];
__device__ __align__(128) char g_h1H[RB * 65536];      // h1 A-images (per rowblock, 4 kc x 16KB)
__device__ __align__(128) char g_h1L[RB * 65536];

// ---------------- helpers ----------------
template <int S>
__device__ __forceinline__ uint32_t swz(uint32_t off) {
    return off ^ (((off >> S) & 7u) << 4);
}
// column-pair permutation so MMA C-fragments give 4 consecutive logical cols
__device__ __forceinline__ int permp(int np) {
    return (np & ~7) | ((np & 7) >> 1) | ((np & 1) << 2);
}
__device__ __forceinline__ uint32_t smem_u32(const void* p) {
    uint32_t a;
    asm("{ .reg .u64 t; cvta.to.shared.u64 t, %1; cvt.u32.u64 %0, t; }" : "=r"(a) : "l"(p));
    return a;
}
__device__ __forceinline__ void ldsm4(uint32_t r[4], uint32_t a) {
    asm volatile("ldmatrix.sync.aligned.m8n8.x4.shared.b16 {%0,%1,%2,%3}, [%4];"
                 : "=r"(r[0]), "=r"(r[1]), "=r"(r[2]), "=r"(r[3]) : "r"(a));
}
__device__ __forceinline__ void ldsm4t(uint32_t r[4], uint32_t a) {
    asm volatile("ldmatrix.sync.aligned.m8n8.x4.trans.shared.b16 {%0,%1,%2,%3}, [%4];"
                 : "=r"(r[0]), "=r"(r[1]), "=r"(r[2]), "=r"(r[3]) : "r"(a));
}
__device__ __forceinline__ void mma16816(float d[4], const uint32_t a[4], const uint32_t b[2]) {
    asm volatile("mma.sync.aligned.m16n8k16.row.col.f32.bf16.bf16.f32 "
                 "{%0,%1,%2,%3}, {%4,%5,%6,%7}, {%8,%9}, {%0,%1,%2,%3};"
                 : "+f"(d[0]), "+f"(d[1]), "+f"(d[2]), "+f"(d[3])
                 : "r"(a[0]), "r"(a[1]), "r"(a[2]), "r"(a[3]), "r"(b[0]), "r"(b[1]));
}
__device__ __forceinline__ void red4(float* a, float4 v) {
    asm volatile("red.global.add.v4.f32 [%0], {%1,%2,%3,%4};"
                 :: "l"(a), "f"(v.x), "f"(v.y), "f"(v.z), "f"(v.w));
}
__device__ __forceinline__ void cpa16(uint32_t dst, const void* src) {
    asm volatile("cp.async.cg.shared.global [%0], [%1], 16;" :: "r"(dst), "l"(src));
}
__device__ __forceinline__ void cpa_commit() { asm volatile("cp.async.commit_group;"); }
__device__ __forceinline__ void cpa_wait0()  { asm volatile("cp.async.wait_group 0;"); }

__device__ __forceinline__ void store_pair(char* bH, char* bL, uint32_t off, float2 v) {
    __nv_bfloat16 h0 = __float2bfloat16(v.x), h1 = __float2bfloat16(v.y);
    __nv_bfloat16 l0 = __float2bfloat16(v.x - __bfloat162float(h0));
    __nv_bfloat16 l1 = __float2bfloat16(v.y - __bfloat162float(h1));
    *(__nv_bfloat162*)(bH + off) = __halves2bfloat162(h0, h1);
    *(__nv_bfloat162*)(bL + off) = __halves2bfloat162(l0, l1);
}

// ---------------------------------------------------------------------------
// Shared mainloop chunk: acc[128-row-tile] += A[128x64] @ B[64 x (64 cols)]
// A: 128B rows swz<7>; B: 512B rows swz<9>. 3-pass bf16 split with
// register-resident fragments (Ah*Bh + Ah*Bl + Al*Bh).
// Warp covers rows [mbase, mbase+32), cols [nbase, nbase+64).
// ---------------------------------------------------------------------------
__device__ __forceinline__ void mma_chunk(float acc[2][8][4],
    uint32_t aH, uint32_t aL, uint32_t bH, uint32_t bL,
    int mbase, int nbase, int l)
{
    const int lr = l & 7, lg8 = ((l >> 3) & 1) * 8, lh8 = (l >> 4) * 8;
    #pragma unroll
    for (int ks = 0; ks < 4; ks++) {
        uint32_t a[2][4], bh[8][2], bl[8][2];
        #pragma unroll
        for (int mf = 0; mf < 2; mf++)
            ldsm4(a[mf], aH + swz<7>((uint32_t)((mbase + mf * 16 + lr + lg8) * 128
                                                + (ks * 16 + lh8) * 2)));
        #pragma unroll
        for (int nq = 0; nq < 4; nq++) {
            uint32_t r4[4];
            uint32_t off = swz<9>((uint32_t)((ks * 16 + lr + lg8) * 512
                                             + (nbase + nq * 16 + lh8) * 2));
            ldsm4t(r4, bH + off);
            bh[2 * nq][0] = r4[0]; bh[2 * nq][1] = r4[1];
            bh[2 * nq + 1][0] = r4[2]; bh[2 * nq + 1][1] = r4[3];
            ldsm4t(r4, bL + off);
            bl[2 * nq][0] = r4[0]; bl[2 * nq][1] = r4[1];
            bl[2 * nq + 1][0] = r4[2]; bl[2 * nq + 1][1] = r4[3];
        }
        #pragma unroll
        for (int mf = 0; mf < 2; mf++)
            #pragma unroll
            for (int nf = 0; nf < 8; nf++)
                mma16816(acc[mf][nf], a[mf], bh[nf]);
        #pragma unroll
        for (int mf = 0; mf < 2; mf++)
            #pragma unroll
            for (int nf = 0; nf < 8; nf++)
                mma16816(acc[mf][nf], a[mf], bl[nf]);
        #pragma unroll
        for (int mf = 0; mf < 2; mf++)
            ldsm4(a[mf], aL + swz<7>((uint32_t)((mbase + mf * 16 + lr + lg8) * 128
                                                + (ks * 16 + lh8) * 2)));
        #pragma unroll
        for (int mf = 0; mf < 2; mf++)
            #pragma unroll
            for (int nf = 0; nf < 8; nf++)
                mma16816(acc[mf][nf], a[mf], bh[nf]);
    }
}

// ---------------------------------------------------------------------------
// k_prep: build bf16 hi/lo weight images (smem byte layout, swizzle+perm baked)
// ---------------------------------------------------------------------------
__global__ __launch_bounds__(256) void k_prep(const float* __restrict__ We,
                                              const float* __restrict__ W1,
                                              const float* __restrict__ W2)
{
    int i = blockIdx.x * 256 + threadIdx.x;
    if (i < 8192) {                       // We: 64k x 128 pairs
        int k = i >> 7, np = i & 127;
        uint32_t off = swz<9>((uint32_t)(k * 512 + permp(np) * 4));
        store_pair(g_weH, g_weL, off, ((const float2*)We)[i]);
    } else if (i < 40960) {               // W1: 4 chunks x 64k x 128 pairs
        int j = i - 8192;
        int kc = j >> 13, k = (j >> 7) & 63, np = j & 127;
        uint32_t off = (uint32_t)(kc * 32768) + swz<9>((uint32_t)(k * 512 + permp(np) * 4));
        store_pair(g_w1H, g_w1L, off, ((const float2*)W1)[j]);
    } else if (i < 73728) {               // W2
        int j = i - 40960;
        int kc = j >> 13, k = (j >> 7) & 63, np = j & 127;
        uint32_t off = (uint32_t)(kc * 32768) + swz<9>((uint32_t)(k * 512 + permp(np) * 4));
        store_pair(g_w2H, g_w2L, off, ((const float2*)W2)[j]);
    }
}

// ---------------------------------------------------------------------------
// k_init: z = x
// ---------------------------------------------------------------------------
__global__ __launch_bounds__(256) void k_init(const float4* __restrict__ x) {
    int i = blockIdx.x * 256 + threadIdx.x;
    reinterpret_cast<float4*>(g_z)[i] = x[i];
}

// ---------------------------------------------------------------------------
// k_edge: CTA = 128 edges; msg = relu(ea@We + x[src] + be) -> red.v4 g_z[dst]
// 256 threads (wm 4 x wn 2), N in 2 halves, single __syncthreads.
// ---------------------------------------------------------------------------
#define E_AH 0
#define E_AL 16384
#define E_BH 32768
#define E_BL 65536
#define E_SMEM 98304

__global__ __launch_bounds__(256, 2) void k_edge(
    const float* __restrict__ x, const int* __restrict__ eidx,
    const float* __restrict__ ea, const float* __restrict__ be)
{
    extern __shared__ char sm[];
    const int t = threadIdx.x, w = t >> 5, l = t & 31;
    const int wm = w & 3, wn = w >> 2, j = l & 3;
    const uint32_t sb = smem_u32(sm);

    // B: bulk cp.async of pre-built We images
    #pragma unroll
    for (int i0 = 0; i0 < 8; i0++) {
        int i = i0 * 256 + t;
        cpa16(sb + E_BH + i * 16, g_weH + i * 16);
        cpa16(sb + E_BL + i * 16, g_weL + i * 16);
    }
    cpa_commit();

    // A: convert edge_attr tile [128][64] to bf16 hi/lo
    const float2* ea2 = (const float2*)(ea + (size_t)blockIdx.x * (128 * 64));
    #pragma unroll
    for (int i0 = 0; i0 < 16; i0++) {
        int i = i0 * 256 + t;
        int r = i >> 5, kp = i & 31;
        store_pair(sm + E_AH, sm + E_AL, swz<7>((uint32_t)(r * 128 + kp * 4)), ea2[i]);
    }
    cpa_wait0();
    __syncthreads();

    // per-thread edge rows (4): wm*32 + mf*16 + rh*8 + (l>>2)
    int si[4], di[4];
    #pragma unroll
    for (int q = 0; q < 4; q++) {
        int r = wm * 32 + (q >> 1) * 16 + (q & 1) * 8 + (l >> 2);
        long long e = (long long)blockIdx.x * 128 + r;
        si[q] = eidx[e]; di[q] = eidx[NE + e];
    }

    #pragma unroll 1
    for (int hf = 0; hf < 2; hf++) {
        float acc[2][8][4];
        #pragma unroll
        for (int mf = 0; mf < 2; mf++)
            #pragma unroll
            for (int nf = 0; nf < 8; nf++) {
                acc[mf][nf][0] = 0.f; acc[mf][nf][1] = 0.f;
                acc[mf][nf][2] = 0.f; acc[mf][nf][3] = 0.f;
            }
        mma_chunk(acc, sb + E_AH, sb + E_AL, sb + E_BH, sb + E_BL,
                  wm * 32, hf * 128 + wn * 64, l);

        #pragma unroll
        for (int mf = 0; mf < 2; mf++)
            #pragma unroll
            for (int rh = 0; rh < 2; rh++) {
                const int q = mf * 2 + rh;
                const float4* xr = (const float4*)(x + (size_t)si[q] * DIM);
                float* zd = g_z + (size_t)di[q] * DIM;
                #pragma unroll
                for (int nq = 0; nq < 4; nq++) {
                    int col = hf * 128 + wn * 64 + nq * 16 + 4 * j;
                    float4 xv = xr[col >> 2];
                    float4 bv = ((const float4*)be)[col >> 2];
                    float4 o;
                    o.x = fmaxf(acc[mf][2 * nq][2 * rh]     + xv.x + bv.x, 0.f);
                    o.y = fmaxf(acc[mf][2 * nq][2 * rh + 1] + xv.y + bv.y, 0.f);
                    o.z = fmaxf(acc[mf][2 * nq + 1][2 * rh]     + xv.z + bv.z, 0.f);
                    o.w = fmaxf(acc[mf][2 * nq + 1][2 * rh + 1] + xv.w + bv.w, 0.f);
                    red4(zd + col, o);
                }
            }
    }
}

// ---------------------------------------------------------------------------
// MLP kernels: 512 threads (wm 4 x wn 4), CTA = 128 rows x 256 cols,
// K=256 in 4 chunks, double-buffered cp.async for B (and A in mlp2).
// ---------------------------------------------------------------------------
#define P_A(buf)  ((buf) * 32768)              // A hi at 0 / 32768
#define P_AL(buf) ((buf) * 32768 + 16384)
#define P_B(buf)  (65536 + (buf) * 65536)      // B hi at 65536 / 131072
#define P_BL(buf) (65536 + (buf) * 65536 + 32768)
#define P_SMEM 196608

// Kernel 3: h1 = relu(z @ W1 + b1) -> bf16 hi/lo A-images for mlp2
__global__ __launch_bounds__(512, 1) void k_mlp1(const float* __restrict__ b1)
{
    extern __shared__ char sm[];
    const int t = threadIdx.x, w = t >> 5, l = t & 31;
    const int wm = w & 3, wn = w >> 2, j = l & 3;
    const uint32_t sb = smem_u32(sm);
    const int rb = blockIdx.x, rowb = rb * 128;

    // prologue: B0 cp.async + A0 convert
    #pragma unroll
    for (int i0 = 0; i0 < 4; i0++) {
        int i = i0 * 512 + t;
        cpa16(sb + P_B(0) + i * 16, g_w1H + i * 16);
        cpa16(sb + P_BL(0) + i * 16, g_w1L + i * 16);
    }
    cpa_commit();
    #pragma unroll
    for (int i0 = 0; i0 < 8; i0++) {
        int i = i0 * 512 + t;
        int r = i >> 5, kp = i & 31;
        int row = min(rowb + r, NN - 1);
        float2 v = *(const float2*)(g_z + (size_t)row * DIM + kp * 2);
        store_pair(sm + P_A(0), sm + P_AL(0), swz<7>((uint32_t)(r * 128 + kp * 4)), v);
    }

    float acc[2][8][4];
    #pragma unroll
    for (int mf = 0; mf < 2; mf++)
        #pragma unroll
        for (int nf = 0; nf < 8; nf++) {
            acc[mf][nf][0] = 0.f; acc[mf][nf][1] = 0.f;
            acc[mf][nf][2] = 0.f; acc[mf][nf][3] = 0.f;
        }

    #pragma unroll 1
    for (int c = 0; c < 4; c++) {
        cpa_wait0();
        __syncthreads();
        if (c < 3) {
            int nb = (c + 1) & 1;
            #pragma unroll
            for (int i0 = 0; i0 < 4; i0++) {
                int i = i0 * 512 + t;
                cpa16(sb + P_B(nb) + i * 16, g_w1H + (c + 1) * 32768 + i * 16);
                cpa16(sb + P_BL(nb) + i * 16, g_w1L + (c + 1) * 32768 + i * 16);
            }
            cpa_commit();
            #pragma unroll
            for (int i0 = 0; i0 < 8; i0++) {
                int i = i0 * 512 + t;
                int r = i >> 5, kp = i & 31;
                int row = min(rowb + r, NN - 1);
                float2 v = *(const float2*)(g_z + (size_t)row * DIM + (c + 1) * 64 + kp * 2);
                store_pair(sm + P_A(nb), sm + P_AL(nb),
                           swz<7>((uint32_t)(r * 128 + kp * 4)), v);
            }
        }
        int cb = c & 1;
        mma_chunk(acc, sb + P_A(cb), sb + P_AL(cb), sb + P_B(cb), sb + P_BL(cb),
                  wm * 32, wn * 64, l);
    }

    // epilogue: relu(+b1) -> h1 images
    #pragma unroll
    for (int mf = 0; mf < 2; mf++)
        #pragma unroll
        for (int rh = 0; rh < 2; rh++) {
            int r = wm * 32 + mf * 16 + rh * 8 + (l >> 2);
            if (rowb + r < NN) {
                #pragma unroll
                for (int nq = 0; nq < 4; nq++) {
                    int col = wn * 64 + nq * 16 + 4 * j;
                    float4 bv = ((const float4*)b1)[col >> 2];
                    float h0 = fmaxf(acc[mf][2 * nq][2 * rh]     + bv.x, 0.f);
                    float h1 = fmaxf(acc[mf][2 * nq][2 * rh + 1] + bv.y, 0.f);
                    float h2 = fmaxf(acc[mf][2 * nq + 1][2 * rh]     + bv.z, 0.f);
                    float h3 = fmaxf(acc[mf][2 * nq + 1][2 * rh + 1] + bv.w, 0.f);
                    __nv_bfloat16 b0 = __float2bfloat16(h0), b1v = __float2bfloat16(h1);
                    __nv_bfloat16 b2 = __float2bfloat16(h2), b3 = __float2bfloat16(h3);
                    __nv_bfloat16 c0 = __float2bfloat16(h0 - __bfloat162float(b0));
                    __nv_bfloat16 c1 = __float2bfloat16(h1 - __bfloat162float(b1v));
                    __nv_bfloat16 c2 = __float2bfloat16(h2 - __bfloat162float(b2));
                    __nv_bfloat16 c3 = __float2bfloat16(h3 - __bfloat162float(b3));
                    int kc = col >> 6, kp = col & 63;
                    uint32_t off = (uint32_t)(rb * 65536 + kc * 16384)
                                 + swz<7>((uint32_t)(r * 128 + kp * 2));
                    __nv_bfloat162 hA = __halves2bfloat162(b0, b1v);
                    __nv_bfloat162 hB = __halves2bfloat162(b2, b3);
                    *(ull*)(g_h1H + off) =
                        ((ull)*(uint32_t*)&hB << 32) | *(uint32_t*)&hA;
                    __nv_bfloat162 lA = __halves2bfloat162(c0, c1);
                    __nv_bfloat162 lB = __halves2bfloat162(c2, c3);
                    *(ull*)(g_h1L + off) =
                        ((ull)*(uint32_t*)&lB << 32) | *(uint32_t*)&lA;
                }
            }
        }
}

// Kernel 4: h = relu(h1 @ W2 + b2) + x -> g_z (pre-LN)
__global__ __launch_bounds__(512, 1) void k_mlp2(const float* __restrict__ x,
                                                 const float* __restrict__ b2)
{
    extern __shared__ char sm[];
    const int t = threadIdx.x, w = t >> 5, l = t & 31;
    const int wm = w & 3, wn = w >> 2, j = l & 3;
    const uint32_t sb = smem_u32(sm);
    const int rb = blockIdx.x, rowb = rb * 128;

    // prologue: B0 + A0 all cp.async
    #pragma unroll
    for (int i0 = 0; i0 < 4; i0++) {
        int i = i0 * 512 + t;
        cpa16(sb + P_B(0) + i * 16, g_w2H + i * 16);
        cpa16(sb + P_BL(0) + i * 16, g_w2L + i * 16);
    }
    #pragma unroll
    for (int i0 = 0; i0 < 2; i0++) {
        int i = i0 * 512 + t;
        cpa16(sb + P_A(0) + i * 16, g_h1H + (size_t)rb * 65536 + i * 16);
        cpa16(sb + P_AL(0) + i * 16, g_h1L + (size_t)rb * 65536 + i * 16);
    }
    cpa_commit();

    float acc[2][8][4];
    #pragma unroll
    for (int mf = 0; mf < 2; mf++)
        #pragma unroll
        for (int nf = 0; nf < 8; nf++) {
            acc[mf][nf][0] = 0.f; acc[mf][nf][1] = 0.f;
            acc[mf][nf][2] = 0.f; acc[mf][nf][3] = 0.f;
        }

    #pragma unroll 1
    for (int c = 0; c < 4; c++) {
        cpa_wait0();
        __syncthreads();
        if (c < 3) {
            int nb = (c + 1) & 1;
            #pragma unroll
            for (int i0 = 0; i0 < 4; i0++) {
                int i = i0 * 512 + t;
                cpa16(sb + P_B(nb) + i * 16, g_w2H + (c + 1) * 32768 + i * 16);
                cpa16(sb + P_BL(nb) + i * 16, g_w2L + (c + 1) * 32768 + i * 16);
            }
            #pragma unroll
            for (int i0 = 0; i0 < 2; i0++) {
                int i = i0 * 512 + t;
                cpa16(sb + P_A(nb) + i * 16,
                      g_h1H + (size_t)rb * 65536 + (c + 1) * 16384 + i * 16);
                cpa16(sb + P_AL(nb) + i * 16,
                      g_h1L + (size_t)rb * 65536 + (c + 1) * 16384 + i * 16);
            }
            cpa_commit();
        }
        int cb = c & 1;
        mma_chunk(acc, sb + P_A(cb), sb + P_AL(cb), sb + P_B(cb), sb + P_BL(cb),
                  wm * 32, wn * 64, l);
    }

    // epilogue: relu(+b2) + x -> g_z
    #pragma unroll
    for (int mf = 0; mf < 2; mf++)
        #pragma unroll
        for (int rh = 0; rh < 2; rh++) {
            int r = wm * 32 + mf * 16 + rh * 8 + (l >> 2);
            int grow = rowb + r;
            if (grow < NN) {
                #pragma unroll
                for (int nq = 0; nq < 4; nq++) {
                    int col = wn * 64 + nq * 16 + 4 * j;
                    float4 bv = ((const float4*)b2)[col >> 2];
                    float4 xv = ((const float4*)(x + (size_t)grow * DIM))[col >> 2];
                    float4 o;
                    o.x = fmaxf(acc[mf][2 * nq][2 * rh]     + bv.x, 0.f) + xv.x;
                    o.y = fmaxf(acc[mf][2 * nq][2 * rh + 1] + bv.y, 0.f) + xv.y;
                    o.z = fmaxf(acc[mf][2 * nq + 1][2 * rh]     + bv.z, 0.f) + xv.z;
                    o.w = fmaxf(acc[mf][2 * nq + 1][2 * rh + 1] + bv.w, 0.f) + xv.w;
                    ((float4*)(g_z + (size_t)grow * DIM))[col >> 2] = o;
                }
            }
        }
}

// Kernel 5: out = LayerNorm(g_z) * gamma + beta    (warp per row)
__global__ __launch_bounds__(256) void k_ln(const float* __restrict__ gamma,
                                            const float* __restrict__ beta,
                                            float* __restrict__ out)
{
    const int w = threadIdx.x >> 5, l = threadIdx.x & 31;
    const int row = blockIdx.x * 8 + w;
    const float4* hr = (const float4*)(g_z + (size_t)row * DIM);
    float4 v0 = hr[l], v1 = hr[32 + l];
    float s = v0.x + v0.y + v0.z + v0.w + v1.x + v1.y + v1.z + v1.w;
    float q = v0.x * v0.x + v0.y * v0.y + v0.z * v0.z + v0.w * v0.w
            + v1.x * v1.x + v1.y * v1.y + v1.z * v1.z + v1.w * v1.w;
    #pragma unroll
    for (int o = 16; o; o >>= 1) {
        s += __shfl_xor_sync(0xffffffffu, s, o);
        q += __shfl_xor_sync(0xffffffffu, q, o);
    }
    float mu = s * (1.0f / 256.0f);
    float var = q * (1.0f / 256.0f) - mu * mu;
    float inv = rsqrtf(var + 1e-5f);
    float4 ga = ((const float4*)gamma)[l], gb = ((const float4*)gamma)[32 + l];
    float4 ba = ((const float4*)beta)[l],  bb = ((const float4*)beta)[32 + l];
    float4 o0, o1;
    o0.x = (v0.x - mu) * inv * ga.x + ba.x;
    o0.y = (v0.y - mu) * inv * ga.y + ba.y;
    o0.z = (v0.z - mu) * inv * ga.z + ba.z;
    o0.w = (v0.w - mu) * inv * ga.w + ba.w;
    o1.x = (v1.x - mu) * inv * gb.x + bb.x;
    o1.y = (v1.y - mu) * inv * gb.y + bb.y;
    o1.z = (v1.z - mu) * inv * gb.z + bb.z;
    o1.w = (v1.w - mu) * inv * gb.w + bb.w;
    ((float4*)(out + (size_t)row * DIM))[l] = o0;
    ((float4*)(out + (size_t)row * DIM))[32 + l] = o1;
}

// ---------------------------------------------------------------------------
extern "C" void kernel_launch(void* const* d_in, const int* in_sizes, int n_in,
                              void* d_out, int out_size)
{
    const float* x     = (const float*)d_in[0];
    const int*   eidx  = (const int*)d_in[1];     // int32 (JAX x64 disabled)
    const float* ea    = (const float*)d_in[2];
    const float* We    = (const float*)d_in[3];
    const float* be    = (const float*)d_in[4];
    const float* W1    = (const float*)d_in[5];
    const float* b1    = (const float*)d_in[6];
    const float* W2    = (const float*)d_in[7];
    const float* b2    = (const float*)d_in[8];
    const float* gamma = (const float*)d_in[9];
    const float* beta  = (const float*)d_in[10];
    float* out         = (float*)d_out;

    cudaFuncSetAttribute(k_edge, cudaFuncAttributeMaxDynamicSharedMemorySize, E_SMEM);
    cudaFuncSetAttribute(k_mlp1, cudaFuncAttributeMaxDynamicSharedMemorySize, P_SMEM);
    cudaFuncSetAttribute(k_mlp2, cudaFuncAttributeMaxDynamicSharedMemorySize, P_SMEM);

    k_prep<<<288, 256>>>(We, W1, W2);
    k_init<<<12500, 256>>>((const float4*)x);
    k_edge<<<6250, 256, E_SMEM>>>(x, eidx, ea, be);
    k_mlp1<<<RB, 512, P_SMEM>>>(b1);
    k_mlp2<<<RB, 512, P_SMEM>>>(x, b2);
    k_ln<<<6250, 256>>>(gamma, beta, out);
}